// round 1
// baseline (speedup 1.0000x reference)
#include <cuda_runtime.h>

typedef unsigned long long u64;
#define DEV __device__ __forceinline__

DEV u64 pk2(float v) {
    u64 r; asm("mov.b64 %0, {%1, %1};" : "=l"(r) : "f"(v)); return r;
}
DEV void fma2(u64& d, u64 a, u64 b) {
    asm("fma.rn.f32x2 %0, %1, %2, %0;" : "+l"(d) : "l"(a), "l"(b));
}

constexpr int BATCH = 16384;
constexpr int F1    = 512;
constexpr int HID   = 256;
constexpr int NOUT  = 128;
constexpr int BT    = 8;      // batch elements per CTA
constexpr int MT    = 96;     // rows per CTA (= BT * 12 leads)
constexpr int KB    = 16;     // k-slice
constexpr int THREADS = 512;
constexpr int HSTR  = 264;    // Hs row stride (pad vs bank conflicts, /4 aligned)
constexpr int XSTR  = 20;     // Xs row stride

constexpr int HS_ELEMS = MT * HSTR;        // 25344
constexpr int WS_ELEMS = 2 * KB * HID;     // 8192
constexpr int XS_ELEMS = 2 * MT * XSTR;    // 3840
constexpr int A_ELEMS  = 144;
constexpr int SMEM_BYTES = (HS_ELEMS + WS_ELEMS + XS_ELEMS + A_ELEMS + 16) * 4;

// Mix P (in Hs) with A_norm over leads, add bias, optional relu, write back to Hs.
template<int NJ, bool RELU>
DEV void mix_store(float* Hs, const float* Am, const float* __restrict__ bias,
                   int tx, int r0)
{
    float h[3][NJ * 4];
    #pragma unroll
    for (int i = 0; i < 3; i++)
        #pragma unroll
        for (int j = 0; j < NJ * 4; j++) h[i][j] = 0.f;

    #pragma unroll
    for (int i = 0; i < 3; i++) {
        int r = r0 + i;
        int base = (r / 12) * 12;
        int lead = r - base;
        for (int m = 0; m < 12; m++) {
            float w = Am[lead * 12 + m];
            if (w == 0.f) continue;
            #pragma unroll
            for (int j = 0; j < NJ; j++) {
                float4 p = *(const float4*)(Hs + (base + m) * HSTR + (tx << 2) + (j << 6));
                h[i][4*j+0] += w * p.x;
                h[i][4*j+1] += w * p.y;
                h[i][4*j+2] += w * p.z;
                h[i][4*j+3] += w * p.w;
            }
        }
    }
    __syncthreads();   // all reads of P complete before overwrite
    #pragma unroll
    for (int i = 0; i < 3; i++) {
        #pragma unroll
        for (int j = 0; j < NJ; j++) {
            int col = (tx << 2) + (j << 6);
            float4 bv = *(const float4*)(bias + col);
            float4 o;
            o.x = h[i][4*j+0] + bv.x;
            o.y = h[i][4*j+1] + bv.y;
            o.z = h[i][4*j+2] + bv.z;
            o.w = h[i][4*j+3] + bv.w;
            if (RELU) {
                o.x = fmaxf(o.x, 0.f); o.y = fmaxf(o.y, 0.f);
                o.z = fmaxf(o.z, 0.f); o.w = fmaxf(o.w, 0.f);
            }
            *(float4*)(Hs + (r0 + i) * HSTR + col) = o;
        }
    }
    __syncthreads();
}

__global__ void __launch_bounds__(THREADS, 1)
ecg_fused(const float* __restrict__ x,
          const float* __restrict__ W1, const float* __restrict__ b1,
          const float* __restrict__ W2, const float* __restrict__ b2,
          const float* __restrict__ W3, const float* __restrict__ b3,
          float* __restrict__ out)
{
    extern __shared__ float sm[];
    float* Hs  = sm;
    float* Wsb = sm + HS_ELEMS;
    float* Xs  = Wsb + WS_ELEMS;
    float* Am  = Xs + XS_ELEMS;

    const int tid = threadIdx.x;
    const int tx  = tid & 15;
    const int ty  = tid >> 4;
    const int r0  = ty * 3;
    const long long rowbase = (long long)blockIdx.x * MT;

    // Build A_norm (12x12) once per CTA: adj + 2*I (buffer eye + PyG self-loop), sym-normalized.
    if (tid == 0) {
        float a[12][12];
        for (int i = 0; i < 12; i++)
            for (int j = 0; j < 12; j++) a[i][j] = (i == j) ? 2.0f : 0.0f;
        const int ei[15] = {0,0,1,0,1,2,0,1,1,2,6,7,8,9,10};
        const int ej[15] = {1,2,2,3,3,3,4,4,5,5,7,8,9,10,11};
        for (int e = 0; e < 15; e++) { a[ei[e]][ej[e]] = 1.0f; a[ej[e]][ei[e]] = 1.0f; }
        float dinv[12];
        for (int i = 0; i < 12; i++) {
            float s = 0.f;
            for (int j = 0; j < 12; j++) s += a[i][j];
            dinv[i] = 1.0f / sqrtf(s);
        }
        for (int i = 0; i < 12; i++)
            for (int j = 0; j < 12; j++)
                Am[i * 12 + j] = dinv[i] * a[i][j] * dinv[j];
    }

    // staging thread assignments (N=256 weight slices: 2 float4 each; X: 4 thr/row)
    const int wk = tid >> 5;           // 0..15 (k within slice)
    const int wn = (tid & 31) << 2;    // 0..124
    const int xr = tid >> 2;           // 0..127 (only <96 active)
    const int xc = (tid & 3) << 2;     // 0,4,8,12
    const bool xact = tid < 384;

    // ================= Layer 1: P = Xtile(96x512) @ W1(512x256) =================
    u64 acc[3][8];
    #pragma unroll
    for (int i = 0; i < 3; i++)
        #pragma unroll
        for (int j = 0; j < 8; j++) acc[i][j] = 0ull;

    {
        float4 w0 = *(const float4*)(W1 + (size_t)wk * HID + wn);
        float4 w1 = *(const float4*)(W1 + (size_t)wk * HID + wn + 128);
        *(float4*)(Wsb + wk * HID + wn)       = w0;
        *(float4*)(Wsb + wk * HID + wn + 128) = w1;
        if (xact) {
            float4 xv = *(const float4*)(x + (rowbase + xr) * F1 + xc);
            *(float4*)(Xs + xr * XSTR + xc) = xv;
        }
    }
    __syncthreads();

    for (int kb = 0; kb < F1; kb += KB) {
        const int cur = (kb / KB) & 1;
        const int nxt = cur ^ 1;
        float4 nw0, nw1, nx;
        const bool more = (kb + KB) < F1;
        if (more) {
            nw0 = *(const float4*)(W1 + (size_t)(kb + KB + wk) * HID + wn);
            nw1 = *(const float4*)(W1 + (size_t)(kb + KB + wk) * HID + wn + 128);
            if (xact) nx = *(const float4*)(x + (rowbase + xr) * F1 + kb + KB + xc);
        }
        const float* Wc = Wsb + cur * KB * HID;
        const float* Xc = Xs + cur * MT * XSTR;
        #pragma unroll
        for (int k = 0; k < KB; k++) {
            u64 a0 = pk2(Xc[(r0 + 0) * XSTR + k]);
            u64 a1 = pk2(Xc[(r0 + 1) * XSTR + k]);
            u64 a2 = pk2(Xc[(r0 + 2) * XSTR + k]);
            #pragma unroll
            for (int j = 0; j < 4; j++) {
                ulonglong2 w = *(const ulonglong2*)(Wc + k * HID + (tx << 2) + (j << 6));
                fma2(acc[0][2*j],   a0, w.x); fma2(acc[0][2*j+1], a0, w.y);
                fma2(acc[1][2*j],   a1, w.x); fma2(acc[1][2*j+1], a1, w.y);
                fma2(acc[2][2*j],   a2, w.x); fma2(acc[2][2*j+1], a2, w.y);
            }
        }
        if (more) {
            *(float4*)(Wsb + nxt * KB * HID + wk * HID + wn)       = nw0;
            *(float4*)(Wsb + nxt * KB * HID + wk * HID + wn + 128) = nw1;
            if (xact) *(float4*)(Xs + nxt * MT * XSTR + xr * XSTR + xc) = nx;
        }
        __syncthreads();
    }

    // P -> Hs (pairs are adjacent columns: col = tx*4 + (j>>1)*64 + (j&1)*2)
    #pragma unroll
    for (int i = 0; i < 3; i++)
        #pragma unroll
        for (int j = 0; j < 8; j++)
            *(u64*)(Hs + (r0 + i) * HSTR + (tx << 2) + ((j >> 1) << 6) + ((j & 1) << 1)) = acc[i][j];
    __syncthreads();
    mix_store<4, true>(Hs, Am, b1, tx, r0);

    // ================= Layer 2: P = H1(96x256) @ W2(256x256) =================
    #pragma unroll
    for (int i = 0; i < 3; i++)
        #pragma unroll
        for (int j = 0; j < 8; j++) acc[i][j] = 0ull;

    {
        float4 w0 = *(const float4*)(W2 + (size_t)wk * HID + wn);
        float4 w1 = *(const float4*)(W2 + (size_t)wk * HID + wn + 128);
        *(float4*)(Wsb + wk * HID + wn)       = w0;
        *(float4*)(Wsb + wk * HID + wn + 128) = w1;
    }
    __syncthreads();

    for (int kb = 0; kb < HID; kb += KB) {
        const int cur = (kb / KB) & 1;
        const int nxt = cur ^ 1;
        float4 nw0, nw1;
        const bool more = (kb + KB) < HID;
        if (more) {
            nw0 = *(const float4*)(W2 + (size_t)(kb + KB + wk) * HID + wn);
            nw1 = *(const float4*)(W2 + (size_t)(kb + KB + wk) * HID + wn + 128);
        }
        const float* Wc = Wsb + cur * KB * HID;
        #pragma unroll
        for (int k = 0; k < KB; k++) {
            u64 a0 = pk2(Hs[(r0 + 0) * HSTR + kb + k]);
            u64 a1 = pk2(Hs[(r0 + 1) * HSTR + kb + k]);
            u64 a2 = pk2(Hs[(r0 + 2) * HSTR + kb + k]);
            #pragma unroll
            for (int j = 0; j < 4; j++) {
                ulonglong2 w = *(const ulonglong2*)(Wc + k * HID + (tx << 2) + (j << 6));
                fma2(acc[0][2*j],   a0, w.x); fma2(acc[0][2*j+1], a0, w.y);
                fma2(acc[1][2*j],   a1, w.x); fma2(acc[1][2*j+1], a1, w.y);
                fma2(acc[2][2*j],   a2, w.x); fma2(acc[2][2*j+1], a2, w.y);
            }
        }
        if (more) {
            *(float4*)(Wsb + nxt * KB * HID + wk * HID + wn)       = nw0;
            *(float4*)(Wsb + nxt * KB * HID + wk * HID + wn + 128) = nw1;
        }
        __syncthreads();
    }

    #pragma unroll
    for (int i = 0; i < 3; i++)
        #pragma unroll
        for (int j = 0; j < 8; j++)
            *(u64*)(Hs + (r0 + i) * HSTR + (tx << 2) + ((j >> 1) << 6) + ((j & 1) << 1)) = acc[i][j];
    __syncthreads();
    mix_store<4, true>(Hs, Am, b2, tx, r0);

    // ================= Layer 3: P = H2(96x256) @ W3(256x128) =================
    u64 acc3[3][4];
    #pragma unroll
    for (int i = 0; i < 3; i++)
        #pragma unroll
        for (int j = 0; j < 4; j++) acc3[i][j] = 0ull;

    // W3 slice: 16x128 floats -> 1 float4/thread
    {
        float4 w0 = *(const float4*)(W3 + (size_t)wk * NOUT + wn);
        *(float4*)(Wsb + wk * NOUT + wn) = w0;
    }
    __syncthreads();

    for (int kb = 0; kb < HID; kb += KB) {
        const int cur = (kb / KB) & 1;
        const int nxt = cur ^ 1;
        float4 nw0;
        const bool more = (kb + KB) < HID;
        if (more)
            nw0 = *(const float4*)(W3 + (size_t)(kb + KB + wk) * NOUT + wn);
        const float* Wc = Wsb + cur * KB * NOUT;
        #pragma unroll
        for (int k = 0; k < KB; k++) {
            u64 a0 = pk2(Hs[(r0 + 0) * HSTR + kb + k]);
            u64 a1 = pk2(Hs[(r0 + 1) * HSTR + kb + k]);
            u64 a2 = pk2(Hs[(r0 + 2) * HSTR + kb + k]);
            #pragma unroll
            for (int j = 0; j < 2; j++) {
                ulonglong2 w = *(const ulonglong2*)(Wc + k * NOUT + (tx << 2) + (j << 6));
                fma2(acc3[0][2*j],   a0, w.x); fma2(acc3[0][2*j+1], a0, w.y);
                fma2(acc3[1][2*j],   a1, w.x); fma2(acc3[1][2*j+1], a1, w.y);
                fma2(acc3[2][2*j],   a2, w.x); fma2(acc3[2][2*j+1], a2, w.y);
            }
        }
        if (more)
            *(float4*)(Wsb + nxt * KB * NOUT + wk * NOUT + wn) = nw0;
        __syncthreads();
    }

    #pragma unroll
    for (int i = 0; i < 3; i++)
        #pragma unroll
        for (int j = 0; j < 4; j++)
            *(u64*)(Hs + (r0 + i) * HSTR + (tx << 2) + ((j >> 1) << 6) + ((j & 1) << 1)) = acc3[i][j];
    __syncthreads();
    mix_store<2, false>(Hs, Am, b3, tx, r0);

    // ================= Epilogue: mean/max over 12 leads =================
    const long long obase = (long long)blockIdx.x * BT;
    #pragma unroll
    for (int q = 0; q < 2; q++) {
        int p = tid * 2 + q;          // 0..1023
        int b = p >> 7;               // 0..7
        int c = p & 127;
        const float* hp = Hs + (b * 12) * HSTR + c;
        float s = 0.f, mx = -3.402823466e38f;
        #pragma unroll
        for (int m = 0; m < 12; m++) {
            float v = hp[m * HSTR];
            s += v;
            mx = fmaxf(mx, v);
        }
        float* op = out + (obase + b) * 256;
        op[c]       = s * (1.0f / 12.0f);
        op[128 + c] = mx;
    }
}

extern "C" void kernel_launch(void* const* d_in, const int* in_sizes, int n_in,
                              void* d_out, int out_size)
{
    const float* x  = (const float*)d_in[0];
    const float* W1 = (const float*)d_in[1];
    const float* b1 = (const float*)d_in[2];
    const float* W2 = (const float*)d_in[3];
    const float* b2 = (const float*)d_in[4];
    const float* W3 = (const float*)d_in[5];
    const float* b3 = (const float*)d_in[6];
    float* out = (float*)d_out;

    cudaFuncSetAttribute(ecg_fused, cudaFuncAttributeMaxDynamicSharedMemorySize, SMEM_BYTES);
    ecg_fused<<<BATCH / BT, THREADS, SMEM_BYTES>>>(x, W1, b1, W2, b2, W3, b3, out);
}

// round 2
// speedup vs baseline: 1.0002x; 1.0002x over previous
#include <cuda_runtime.h>

typedef unsigned long long u64;
#define DEV __device__ __forceinline__

DEV u64 pk2(float v) {
    u64 r; asm("mov.b64 %0, {%1, %1};" : "=l"(r) : "f"(v)); return r;
}
DEV void fma2(u64& d, u64 a, u64 b) {
    asm("fma.rn.f32x2 %0, %1, %2, %0;" : "+l"(d) : "l"(a), "l"(b));
}

constexpr int BATCH = 16384;
constexpr int F1    = 512;
constexpr int HID   = 256;
constexpr int NOUT  = 128;
constexpr int BT    = 8;      // batch elements per CTA
constexpr int MT    = 96;     // rows per CTA (= BT * 12 leads)
constexpr int KB    = 16;     // k-slice
constexpr int THREADS = 512;
constexpr int HSTR  = 264;    // Hs row stride (pad vs bank conflicts, /4 aligned)
constexpr int XSTR  = 20;     // Xs row stride

constexpr int HS_ELEMS = MT * HSTR;        // 25344
constexpr int WS_ELEMS = 2 * KB * HID;     // 8192
constexpr int XS_ELEMS = 2 * MT * XSTR;    // 3840
constexpr int A_ELEMS  = 144;
constexpr int SMEM_BYTES = (HS_ELEMS + WS_ELEMS + XS_ELEMS + A_ELEMS + 16) * 4;

// Mix P (in Hs) with A_norm over leads, add bias, optional relu, write back to Hs.
template<int NJ, bool RELU>
DEV void mix_store(float* Hs, const float* Am, const float* __restrict__ bias,
                   int tx, int r0)
{
    float h[3][NJ * 4];
    #pragma unroll
    for (int i = 0; i < 3; i++)
        #pragma unroll
        for (int j = 0; j < NJ * 4; j++) h[i][j] = 0.f;

    #pragma unroll
    for (int i = 0; i < 3; i++) {
        int r = r0 + i;
        int base = (r / 12) * 12;
        int lead = r - base;
        for (int m = 0; m < 12; m++) {
            float w = Am[lead * 12 + m];
            if (w == 0.f) continue;
            #pragma unroll
            for (int j = 0; j < NJ; j++) {
                float4 p = *(const float4*)(Hs + (base + m) * HSTR + (tx << 2) + (j << 6));
                h[i][4*j+0] += w * p.x;
                h[i][4*j+1] += w * p.y;
                h[i][4*j+2] += w * p.z;
                h[i][4*j+3] += w * p.w;
            }
        }
    }
    __syncthreads();   // all reads of P complete before overwrite
    #pragma unroll
    for (int i = 0; i < 3; i++) {
        #pragma unroll
        for (int j = 0; j < NJ; j++) {
            int col = (tx << 2) + (j << 6);
            float4 bv = *(const float4*)(bias + col);
            float4 o;
            o.x = h[i][4*j+0] + bv.x;
            o.y = h[i][4*j+1] + bv.y;
            o.z = h[i][4*j+2] + bv.z;
            o.w = h[i][4*j+3] + bv.w;
            if (RELU) {
                o.x = fmaxf(o.x, 0.f); o.y = fmaxf(o.y, 0.f);
                o.z = fmaxf(o.z, 0.f); o.w = fmaxf(o.w, 0.f);
            }
            *(float4*)(Hs + (r0 + i) * HSTR + col) = o;
        }
    }
    __syncthreads();
}

__global__ void __launch_bounds__(THREADS, 1)
ecg_fused(const float* __restrict__ x,
          const float* __restrict__ W1, const float* __restrict__ b1,
          const float* __restrict__ W2, const float* __restrict__ b2,
          const float* __restrict__ W3, const float* __restrict__ b3,
          float* __restrict__ out)
{
    extern __shared__ float sm[];
    float* Hs  = sm;
    float* Wsb = sm + HS_ELEMS;
    float* Xs  = Wsb + WS_ELEMS;
    float* Am  = Xs + XS_ELEMS;

    const int tid = threadIdx.x;
    const int tx  = tid & 15;
    const int ty  = tid >> 4;
    const int r0  = ty * 3;
    const long long rowbase = (long long)blockIdx.x * MT;

    // Build A_norm (12x12) once per CTA: adj + 2*I (buffer eye + PyG self-loop), sym-normalized.
    if (tid == 0) {
        float a[12][12];
        for (int i = 0; i < 12; i++)
            for (int j = 0; j < 12; j++) a[i][j] = (i == j) ? 2.0f : 0.0f;
        const int ei[15] = {0,0,1,0,1,2,0,1,1,2,6,7,8,9,10};
        const int ej[15] = {1,2,2,3,3,3,4,4,5,5,7,8,9,10,11};
        for (int e = 0; e < 15; e++) { a[ei[e]][ej[e]] = 1.0f; a[ej[e]][ei[e]] = 1.0f; }
        float dinv[12];
        for (int i = 0; i < 12; i++) {
            float s = 0.f;
            for (int j = 0; j < 12; j++) s += a[i][j];
            dinv[i] = 1.0f / sqrtf(s);
        }
        for (int i = 0; i < 12; i++)
            for (int j = 0; j < 12; j++)
                Am[i * 12 + j] = dinv[i] * a[i][j] * dinv[j];
    }

    // staging thread assignments (N=256 weight slices: 2 float4 each; X: 4 thr/row)
    const int wk = tid >> 5;           // 0..15 (k within slice)
    const int wn = (tid & 31) << 2;    // 0..124
    const int xr = tid >> 2;           // 0..127 (only <96 active)
    const int xc = (tid & 3) << 2;     // 0,4,8,12
    const bool xact = tid < 384;

    // ================= Layer 1: P = Xtile(96x512) @ W1(512x256) =================
    u64 acc[3][8];
    #pragma unroll
    for (int i = 0; i < 3; i++)
        #pragma unroll
        for (int j = 0; j < 8; j++) acc[i][j] = 0ull;

    {
        float4 w0 = *(const float4*)(W1 + (size_t)wk * HID + wn);
        float4 w1 = *(const float4*)(W1 + (size_t)wk * HID + wn + 128);
        *(float4*)(Wsb + wk * HID + wn)       = w0;
        *(float4*)(Wsb + wk * HID + wn + 128) = w1;
        if (xact) {
            float4 xv = *(const float4*)(x + (rowbase + xr) * F1 + xc);
            *(float4*)(Xs + xr * XSTR + xc) = xv;
        }
    }
    __syncthreads();

    for (int kb = 0; kb < F1; kb += KB) {
        const int cur = (kb / KB) & 1;
        const int nxt = cur ^ 1;
        float4 nw0, nw1, nx;
        const bool more = (kb + KB) < F1;
        if (more) {
            nw0 = *(const float4*)(W1 + (size_t)(kb + KB + wk) * HID + wn);
            nw1 = *(const float4*)(W1 + (size_t)(kb + KB + wk) * HID + wn + 128);
            if (xact) nx = *(const float4*)(x + (rowbase + xr) * F1 + kb + KB + xc);
        }
        const float* Wc = Wsb + cur * KB * HID;
        const float* Xc = Xs + cur * MT * XSTR;
        #pragma unroll
        for (int k = 0; k < KB; k++) {
            u64 a0 = pk2(Xc[(r0 + 0) * XSTR + k]);
            u64 a1 = pk2(Xc[(r0 + 1) * XSTR + k]);
            u64 a2 = pk2(Xc[(r0 + 2) * XSTR + k]);
            #pragma unroll
            for (int j = 0; j < 4; j++) {
                ulonglong2 w = *(const ulonglong2*)(Wc + k * HID + (tx << 2) + (j << 6));
                fma2(acc[0][2*j],   a0, w.x); fma2(acc[0][2*j+1], a0, w.y);
                fma2(acc[1][2*j],   a1, w.x); fma2(acc[1][2*j+1], a1, w.y);
                fma2(acc[2][2*j],   a2, w.x); fma2(acc[2][2*j+1], a2, w.y);
            }
        }
        if (more) {
            *(float4*)(Wsb + nxt * KB * HID + wk * HID + wn)       = nw0;
            *(float4*)(Wsb + nxt * KB * HID + wk * HID + wn + 128) = nw1;
            if (xact) *(float4*)(Xs + nxt * MT * XSTR + xr * XSTR + xc) = nx;
        }
        __syncthreads();
    }

    // P -> Hs (pairs are adjacent columns: col = tx*4 + (j>>1)*64 + (j&1)*2)
    #pragma unroll
    for (int i = 0; i < 3; i++)
        #pragma unroll
        for (int j = 0; j < 8; j++)
            *(u64*)(Hs + (r0 + i) * HSTR + (tx << 2) + ((j >> 1) << 6) + ((j & 1) << 1)) = acc[i][j];
    __syncthreads();
    mix_store<4, true>(Hs, Am, b1, tx, r0);

    // ================= Layer 2: P = H1(96x256) @ W2(256x256) =================
    #pragma unroll
    for (int i = 0; i < 3; i++)
        #pragma unroll
        for (int j = 0; j < 8; j++) acc[i][j] = 0ull;

    {
        float4 w0 = *(const float4*)(W2 + (size_t)wk * HID + wn);
        float4 w1 = *(const float4*)(W2 + (size_t)wk * HID + wn + 128);
        *(float4*)(Wsb + wk * HID + wn)       = w0;
        *(float4*)(Wsb + wk * HID + wn + 128) = w1;
    }
    __syncthreads();

    for (int kb = 0; kb < HID; kb += KB) {
        const int cur = (kb / KB) & 1;
        const int nxt = cur ^ 1;
        float4 nw0, nw1;
        const bool more = (kb + KB) < HID;
        if (more) {
            nw0 = *(const float4*)(W2 + (size_t)(kb + KB + wk) * HID + wn);
            nw1 = *(const float4*)(W2 + (size_t)(kb + KB + wk) * HID + wn + 128);
        }
        const float* Wc = Wsb + cur * KB * HID;
        #pragma unroll
        for (int k = 0; k < KB; k++) {
            u64 a0 = pk2(Hs[(r0 + 0) * HSTR + kb + k]);
            u64 a1 = pk2(Hs[(r0 + 1) * HSTR + kb + k]);
            u64 a2 = pk2(Hs[(r0 + 2) * HSTR + kb + k]);
            #pragma unroll
            for (int j = 0; j < 4; j++) {
                ulonglong2 w = *(const ulonglong2*)(Wc + k * HID + (tx << 2) + (j << 6));
                fma2(acc[0][2*j],   a0, w.x); fma2(acc[0][2*j+1], a0, w.y);
                fma2(acc[1][2*j],   a1, w.x); fma2(acc[1][2*j+1], a1, w.y);
                fma2(acc[2][2*j],   a2, w.x); fma2(acc[2][2*j+1], a2, w.y);
            }
        }
        if (more) {
            *(float4*)(Wsb + nxt * KB * HID + wk * HID + wn)       = nw0;
            *(float4*)(Wsb + nxt * KB * HID + wk * HID + wn + 128) = nw1;
        }
        __syncthreads();
    }

    #pragma unroll
    for (int i = 0; i < 3; i++)
        #pragma unroll
        for (int j = 0; j < 8; j++)
            *(u64*)(Hs + (r0 + i) * HSTR + (tx << 2) + ((j >> 1) << 6) + ((j & 1) << 1)) = acc[i][j];
    __syncthreads();
    mix_store<4, true>(Hs, Am, b2, tx, r0);

    // ================= Layer 3: P = H2(96x256) @ W3(256x128) =================
    u64 acc3[3][4];
    #pragma unroll
    for (int i = 0; i < 3; i++)
        #pragma unroll
        for (int j = 0; j < 4; j++) acc3[i][j] = 0ull;

    // W3 slice: 16x128 floats -> 1 float4/thread
    {
        float4 w0 = *(const float4*)(W3 + (size_t)wk * NOUT + wn);
        *(float4*)(Wsb + wk * NOUT + wn) = w0;
    }
    __syncthreads();

    for (int kb = 0; kb < HID; kb += KB) {
        const int cur = (kb / KB) & 1;
        const int nxt = cur ^ 1;
        float4 nw0;
        const bool more = (kb + KB) < HID;
        if (more)
            nw0 = *(const float4*)(W3 + (size_t)(kb + KB + wk) * NOUT + wn);
        const float* Wc = Wsb + cur * KB * NOUT;
        #pragma unroll
        for (int k = 0; k < KB; k++) {
            u64 a0 = pk2(Hs[(r0 + 0) * HSTR + kb + k]);
            u64 a1 = pk2(Hs[(r0 + 1) * HSTR + kb + k]);
            u64 a2 = pk2(Hs[(r0 + 2) * HSTR + kb + k]);
            #pragma unroll
            for (int j = 0; j < 2; j++) {
                ulonglong2 w = *(const ulonglong2*)(Wc + k * NOUT + (tx << 2) + (j << 6));
                fma2(acc3[0][2*j],   a0, w.x); fma2(acc3[0][2*j+1], a0, w.y);
                fma2(acc3[1][2*j],   a1, w.x); fma2(acc3[1][2*j+1], a1, w.y);
                fma2(acc3[2][2*j],   a2, w.x); fma2(acc3[2][2*j+1], a2, w.y);
            }
        }
        if (more)
            *(float4*)(Wsb + nxt * KB * NOUT + wk * NOUT + wn) = nw0;
        __syncthreads();
    }

    #pragma unroll
    for (int i = 0; i < 3; i++)
        #pragma unroll
        for (int j = 0; j < 4; j++)
            *(u64*)(Hs + (r0 + i) * HSTR + (tx << 2) + ((j >> 1) << 6) + ((j & 1) << 1)) = acc3[i][j];
    __syncthreads();
    mix_store<2, false>(Hs, Am, b3, tx, r0);

    // ================= Epilogue: mean/max over 12 leads =================
    const long long obase = (long long)blockIdx.x * BT;
    #pragma unroll
    for (int q = 0; q < 2; q++) {
        int p = tid * 2 + q;          // 0..1023
        int b = p >> 7;               // 0..7
        int c = p & 127;
        const float* hp = Hs + (b * 12) * HSTR + c;
        float s = 0.f, mx = -3.402823466e38f;
        #pragma unroll
        for (int m = 0; m < 12; m++) {
            float v = hp[m * HSTR];
            s += v;
            mx = fmaxf(mx, v);
        }
        float* op = out + (obase + b) * 256;
        op[c]       = s * (1.0f / 12.0f);
        op[128 + c] = mx;
    }
}

extern "C" void kernel_launch(void* const* d_in, const int* in_sizes, int n_in,
                              void* d_out, int out_size)
{
    const float* x  = (const float*)d_in[0];
    const float* W1 = (const float*)d_in[1];
    const float* b1 = (const float*)d_in[2];
    const float* W2 = (const float*)d_in[3];
    const float* b2 = (const float*)d_in[4];
    const float* W3 = (const float*)d_in[5];
    const float* b3 = (const float*)d_in[6];
    float* out = (float*)d_out;

    cudaFuncSetAttribute(ecg_fused, cudaFuncAttributeMaxDynamicSharedMemorySize, SMEM_BYTES);
    ecg_fused<<<BATCH / BT, THREADS, SMEM_BYTES>>>(x, W1, b1, W2, b2, W3, b3, out);
}

// round 3
// speedup vs baseline: 1.1090x; 1.1088x over previous
#include <cuda_runtime.h>

typedef unsigned long long u64;
#define DEV __device__ __forceinline__

DEV u64 pk2(float v) {
    u64 r; asm("mov.b64 %0, {%1, %1};" : "=l"(r) : "f"(v)); return r;
}
DEV void fma2(u64& d, u64 a, u64 b) {
    asm("fma.rn.f32x2 %0, %1, %2, %0;" : "+l"(d) : "l"(a), "l"(b));
}
DEV void upk2(u64 v, float& lo, float& hi) {
    asm("mov.b64 {%0, %1}, %2;" : "=f"(lo), "=f"(hi) : "l"(v));
}

constexpr int BATCH = 16384;
constexpr int F1    = 512;
constexpr int HID   = 256;
constexpr int NOUT  = 128;
constexpr int BT    = 8;      // batch elements per CTA
constexpr int MT    = 96;     // rows per CTA
constexpr int KB    = 16;     // k-slice
constexpr int THREADS = 512;
constexpr int ASTR  = 100;    // transposed activation plane stride (96 rows + pad)

constexpr int HT_ELEMS = HID * ASTR;       // 25600  (k-major activations, in-place mix)
constexpr int WS_ELEMS = 2 * KB * HID;     // 8192   (weight double buffer)
constexpr int XT_ELEMS = 2 * KB * ASTR;    // 3200   (layer-1 x slices, transposed, dbl buf)
constexpr int A_ELEMS  = 144;
constexpr int SMEM_BYTES = (HT_ELEMS + WS_ELEMS + XT_ELEMS + A_ELEMS + 16) * 4;

// Fixed ECG graph neighbor lists (incl. self), 42 nonzeros of the 12x12 A_norm.
__device__ constexpr int NBR_OFF[13] = {0,5,11,16,20,23,26,28,31,34,37,40,42};
__device__ constexpr int NBR[42] = {
    0,1,2,3,4,
    0,1,2,3,4,5,
    0,1,2,3,5,
    0,1,2,3,
    0,1,4,
    1,2,5,
    6,7,
    6,7,8,
    7,8,9,
    8,9,10,
    9,10,11,
    10,11
};

// In-place A-mix on transposed buffer HT[col][12b..12b+11]; optional fused epilogue.
template<int NCOL, bool RELU, bool FINAL>
DEV void mix_phase(float* HT, const float* Am, const float* __restrict__ bias,
                   float* __restrict__ out, long long obase, int tid)
{
    constexpr int NT = NCOL * BT / THREADS;   // tasks per thread
    #pragma unroll
    for (int s = 0; s < NT; s++) {
        int t   = tid + s * THREADS;
        int b   = t & 7;
        int col = t >> 3;
        float* hp = HT + col * ASTR + b * 12;
        float4 h0 = *(const float4*)(hp);
        float4 h1 = *(const float4*)(hp + 4);
        float4 h2 = *(const float4*)(hp + 8);
        float h[12] = {h0.x,h0.y,h0.z,h0.w, h1.x,h1.y,h1.z,h1.w, h2.x,h2.y,h2.z,h2.w};
        float bv = __ldg(bias + col);
        float y[12];
        #pragma unroll
        for (int l = 0; l < 12; l++) {
            float acc = 0.f;
            #pragma unroll
            for (int q = NBR_OFF[l]; q < NBR_OFF[l + 1]; q++) {
                int m = NBR[q];
                acc += Am[l * 12 + m] * h[m];
            }
            y[l] = acc + bv;
            if (RELU) y[l] = fmaxf(y[l], 0.f);
        }
        if (!FINAL) {
            *(float4*)(hp)     = make_float4(y[0], y[1], y[2],  y[3]);
            *(float4*)(hp + 4) = make_float4(y[4], y[5], y[6],  y[7]);
            *(float4*)(hp + 8) = make_float4(y[8], y[9], y[10], y[11]);
        } else {
            float sum = 0.f, mx = -3.402823466e38f;
            #pragma unroll
            for (int l = 0; l < 12; l++) { sum += y[l]; mx = fmaxf(mx, y[l]); }
            float* op = out + (obase + b) * (2 * NOUT);
            op[col]        = sum * (1.0f / 12.0f);
            op[NOUT + col] = mx;
        }
    }
}

__global__ void __launch_bounds__(THREADS, 1)
ecg_fused(const float* __restrict__ x,
          const float* __restrict__ W1, const float* __restrict__ b1,
          const float* __restrict__ W2, const float* __restrict__ b2,
          const float* __restrict__ W3, const float* __restrict__ b3,
          float* __restrict__ out)
{
    extern __shared__ float sm[];
    float* HT  = sm;                  // [HID][ASTR] transposed activations
    float* Wsb = sm + HT_ELEMS;       // weight slices, double buffered
    float* XT  = Wsb + WS_ELEMS;      // layer-1 x slices, transposed, double buffered
    float* Am  = XT + XT_ELEMS;       // 12x12 normalized adjacency

    const int tid  = threadIdx.x;
    const int lane = tid & 31;
    const int w    = tid >> 5;
    const int tx   = lane & 1;        // 2 col sub-groups in warp
    const int tyl  = lane >> 1;       // 16 row threads in warp
    const int rg   = w & 1;           // row group (0..1)
    const int cg   = w >> 1;          // col group (0..7)
    const int r0   = rg * 48 + tyl * 3;           // 3 rows
    const int c0   = cg * 32 + tx * 16;           // 16 cols (N=256 layers)
    const int c0_3 = cg * 16 + tx * 8;            // 8 cols  (N=128 layer)
    const long long rowbase = (long long)blockIdx.x * MT;
    const long long obase   = (long long)blockIdx.x * BT;

    // Build A_norm once per CTA: adj + 2*I (buffer eye + PyG self-loop), sym-normalized.
    if (tid == 0) {
        float a[12][12];
        for (int i = 0; i < 12; i++)
            for (int j = 0; j < 12; j++) a[i][j] = (i == j) ? 2.0f : 0.0f;
        const int ei[15] = {0,0,1,0,1,2,0,1,1,2,6,7,8,9,10};
        const int ej[15] = {1,2,2,3,3,3,4,4,5,5,7,8,9,10,11};
        for (int e = 0; e < 15; e++) { a[ei[e]][ej[e]] = 1.0f; a[ej[e]][ei[e]] = 1.0f; }
        float dinv[12];
        for (int i = 0; i < 12; i++) {
            float s = 0.f;
            for (int j = 0; j < 12; j++) s += a[i][j];
            dinv[i] = 1.0f / sqrtf(s);
        }
        for (int i = 0; i < 12; i++)
            for (int j = 0; j < 12; j++)
                Am[i * 12 + j] = dinv[i] * a[i][j] * dinv[j];
    }

    // staging assignments
    const int wk = tid >> 5;            // 0..15 k within weight slice
    const int wn = (tid & 31) << 2;     // 0..124
    const int xr = tid >> 2;            // 0..127, active <96
    const int xc = (tid & 3) << 2;      // 0,4,8,12
    const bool xact = tid < 384;

    // ================= Layer 1: P = X(96x512) @ W1(512x256) =================
    u64 acc[3][8];
    #pragma unroll
    for (int i = 0; i < 3; i++)
        #pragma unroll
        for (int j = 0; j < 8; j++) acc[i][j] = 0ull;

    {
        float4 w0 = *(const float4*)(W1 + (size_t)wk * HID + wn);
        float4 w1 = *(const float4*)(W1 + (size_t)wk * HID + wn + 128);
        *(float4*)(Wsb + wk * HID + wn)       = w0;
        *(float4*)(Wsb + wk * HID + wn + 128) = w1;
        if (xact) {
            float4 xv = *(const float4*)(x + (rowbase + xr) * F1 + xc);
            XT[(xc + 0) * ASTR + xr] = xv.x;
            XT[(xc + 1) * ASTR + xr] = xv.y;
            XT[(xc + 2) * ASTR + xr] = xv.z;
            XT[(xc + 3) * ASTR + xr] = xv.w;
        }
    }
    __syncthreads();

    for (int kb = 0; kb < F1; kb += KB) {
        const int cur = (kb / KB) & 1;
        const int nxt = cur ^ 1;
        float4 nw0, nw1, nx;
        const bool more = (kb + KB) < F1;
        if (more) {
            nw0 = *(const float4*)(W1 + (size_t)(kb + KB + wk) * HID + wn);
            nw1 = *(const float4*)(W1 + (size_t)(kb + KB + wk) * HID + wn + 128);
            if (xact) nx = *(const float4*)(x + (rowbase + xr) * F1 + kb + KB + xc);
        }
        const float* Wc = Wsb + cur * KB * HID;
        const float* Ac = XT + cur * KB * ASTR;
        #pragma unroll
        for (int k = 0; k < KB; k++) {
            u64 a0 = pk2(Ac[k * ASTR + r0 + 0]);
            u64 a1 = pk2(Ac[k * ASTR + r0 + 1]);
            u64 a2 = pk2(Ac[k * ASTR + r0 + 2]);
            #pragma unroll
            for (int j = 0; j < 4; j++) {
                ulonglong2 wv = *(const ulonglong2*)(Wc + k * HID + c0 + (j << 2));
                fma2(acc[0][2*j],   a0, wv.x); fma2(acc[0][2*j+1], a0, wv.y);
                fma2(acc[1][2*j],   a1, wv.x); fma2(acc[1][2*j+1], a1, wv.y);
                fma2(acc[2][2*j],   a2, wv.x); fma2(acc[2][2*j+1], a2, wv.y);
            }
        }
        if (more) {
            *(float4*)(Wsb + nxt * KB * HID + wk * HID + wn)       = nw0;
            *(float4*)(Wsb + nxt * KB * HID + wk * HID + wn + 128) = nw1;
            if (xact) {
                float* xd = XT + nxt * KB * ASTR;
                xd[(xc + 0) * ASTR + xr] = nx.x;
                xd[(xc + 1) * ASTR + xr] = nx.y;
                xd[(xc + 2) * ASTR + xr] = nx.z;
                xd[(xc + 3) * ASTR + xr] = nx.w;
            }
        }
        __syncthreads();
    }

    // P1 -> HT (transposed). acc[i][jj] = cols c0 + 4*(jj>>1) + 2*(jj&1) + {0,1}
    #pragma unroll
    for (int i = 0; i < 3; i++)
        #pragma unroll
        for (int jj = 0; jj < 8; jj++) {
            int col = c0 + ((jj >> 1) << 2) + ((jj & 1) << 1);
            float lo, hi; upk2(acc[i][jj], lo, hi);
            HT[col * ASTR + r0 + i]       = lo;
            HT[(col + 1) * ASTR + r0 + i] = hi;
        }
    __syncthreads();
    mix_phase<HID, true, false>(HT, Am, b1, out, obase, tid);
    __syncthreads();

    // ================= Layer 2: P = H1(96x256) @ W2(256x256) =================
    #pragma unroll
    for (int i = 0; i < 3; i++)
        #pragma unroll
        for (int j = 0; j < 8; j++) acc[i][j] = 0ull;

    {
        float4 w0 = *(const float4*)(W2 + (size_t)wk * HID + wn);
        float4 w1 = *(const float4*)(W2 + (size_t)wk * HID + wn + 128);
        *(float4*)(Wsb + wk * HID + wn)       = w0;
        *(float4*)(Wsb + wk * HID + wn + 128) = w1;
    }
    __syncthreads();

    for (int kb = 0; kb < HID; kb += KB) {
        const int cur = (kb / KB) & 1;
        const int nxt = cur ^ 1;
        float4 nw0, nw1;
        const bool more = (kb + KB) < HID;
        if (more) {
            nw0 = *(const float4*)(W2 + (size_t)(kb + KB + wk) * HID + wn);
            nw1 = *(const float4*)(W2 + (size_t)(kb + KB + wk) * HID + wn + 128);
        }
        const float* Wc = Wsb + cur * KB * HID;
        const float* Ac = HT + kb * ASTR;
        #pragma unroll
        for (int k = 0; k < KB; k++) {
            u64 a0 = pk2(Ac[k * ASTR + r0 + 0]);
            u64 a1 = pk2(Ac[k * ASTR + r0 + 1]);
            u64 a2 = pk2(Ac[k * ASTR + r0 + 2]);
            #pragma unroll
            for (int j = 0; j < 4; j++) {
                ulonglong2 wv = *(const ulonglong2*)(Wc + k * HID + c0 + (j << 2));
                fma2(acc[0][2*j],   a0, wv.x); fma2(acc[0][2*j+1], a0, wv.y);
                fma2(acc[1][2*j],   a1, wv.x); fma2(acc[1][2*j+1], a1, wv.y);
                fma2(acc[2][2*j],   a2, wv.x); fma2(acc[2][2*j+1], a2, wv.y);
            }
        }
        if (more) {
            *(float4*)(Wsb + nxt * KB * HID + wk * HID + wn)       = nw0;
            *(float4*)(Wsb + nxt * KB * HID + wk * HID + wn + 128) = nw1;
        }
        __syncthreads();
    }
    // all warps done reading HT -> safe to overwrite after the final sync above

    #pragma unroll
    for (int i = 0; i < 3; i++)
        #pragma unroll
        for (int jj = 0; jj < 8; jj++) {
            int col = c0 + ((jj >> 1) << 2) + ((jj & 1) << 1);
            float lo, hi; upk2(acc[i][jj], lo, hi);
            HT[col * ASTR + r0 + i]       = lo;
            HT[(col + 1) * ASTR + r0 + i] = hi;
        }
    __syncthreads();
    mix_phase<HID, true, false>(HT, Am, b2, out, obase, tid);
    __syncthreads();

    // ================= Layer 3: P = H2(96x256) @ W3(256x128) =================
    u64 acc3[3][4];
    #pragma unroll
    for (int i = 0; i < 3; i++)
        #pragma unroll
        for (int j = 0; j < 4; j++) acc3[i][j] = 0ull;

    {
        float4 w0 = *(const float4*)(W3 + (size_t)wk * NOUT + wn);
        *(float4*)(Wsb + wk * NOUT + wn) = w0;
    }
    __syncthreads();

    for (int kb = 0; kb < HID; kb += KB) {
        const int cur = (kb / KB) & 1;
        const int nxt = cur ^ 1;
        float4 nw0;
        const bool more = (kb + KB) < HID;
        if (more)
            nw0 = *(const float4*)(W3 + (size_t)(kb + KB + wk) * NOUT + wn);
        const float* Wc = Wsb + cur * KB * NOUT;
        const float* Ac = HT + kb * ASTR;
        #pragma unroll
        for (int k = 0; k < KB; k++) {
            u64 a0 = pk2(Ac[k * ASTR + r0 + 0]);
            u64 a1 = pk2(Ac[k * ASTR + r0 + 1]);
            u64 a2 = pk2(Ac[k * ASTR + r0 + 2]);
            #pragma unroll
            for (int j = 0; j < 2; j++) {
                ulonglong2 wv = *(const ulonglong2*)(Wc + k * NOUT + c0_3 + (j << 2));
                fma2(acc3[0][2*j],   a0, wv.x); fma2(acc3[0][2*j+1], a0, wv.y);
                fma2(acc3[1][2*j],   a1, wv.x); fma2(acc3[1][2*j+1], a1, wv.y);
                fma2(acc3[2][2*j],   a2, wv.x); fma2(acc3[2][2*j+1], a2, wv.y);
            }
        }
        if (more)
            *(float4*)(Wsb + nxt * KB * NOUT + wk * NOUT + wn) = nw0;
        __syncthreads();
    }

    #pragma unroll
    for (int i = 0; i < 3; i++)
        #pragma unroll
        for (int jj = 0; jj < 4; jj++) {
            int col = c0_3 + ((jj >> 1) << 2) + ((jj & 1) << 1);
            float lo, hi; upk2(acc3[i][jj], lo, hi);
            HT[col * ASTR + r0 + i]       = lo;
            HT[(col + 1) * ASTR + r0 + i] = hi;
        }
    __syncthreads();
    // final mix fused with mean/max epilogue, writes global out
    mix_phase<NOUT, false, true>(HT, Am, b3, out, obase, tid);
}

extern "C" void kernel_launch(void* const* d_in, const int* in_sizes, int n_in,
                              void* d_out, int out_size)
{
    const float* x  = (const float*)d_in[0];
    const float* W1 = (const float*)d_in[1];
    const float* b1 = (const float*)d_in[2];
    const float* W2 = (const float*)d_in[3];
    const float* b2 = (const float*)d_in[4];
    const float* W3 = (const float*)d_in[5];
    const float* b3 = (const float*)d_in[6];
    float* out = (float*)d_out;

    cudaFuncSetAttribute(ecg_fused, cudaFuncAttributeMaxDynamicSharedMemorySize, SMEM_BYTES);
    ecg_fused<<<BATCH / BT, THREADS, SMEM_BYTES>>>(x, W1, b1, W2, b2, W3, b3, out);
}